// round 8
// baseline (speedup 1.0000x reference)
#include <cuda_runtime.h>

#define BB 4
#define NN 50000
#define DD 256
#define EE 800000
#define TAU_MIN_F 0.001f
#define MAX_CORR_F 0.15f
#define XPBD_ITERS_I 4

// Node-major packed positions: x[buf][node][batch][xyz]
// 12 floats (48 B) per node, no padding. 2 * 2.4 MB = 4.8 MB (L2-resident).
#define XN (NN * 12)
__device__ __align__(16) float g_x[2][XN];

// ---------------------------------------------------------------------------
// Kernel 1: x_pred = keypoints + tau * (hand_tokens @ head_w + head_b)
// warp-per-(b,node) row; writes BOTH ping-pong buffers (pre-copies iter 0).
// ---------------------------------------------------------------------------
__global__ void pred_kernel(const float* __restrict__ keypoints,
                            const float* __restrict__ timesteps,
                            const float* __restrict__ hand_tokens,
                            const float* __restrict__ head_w,
                            const float* __restrict__ head_b) {
    __shared__ float sw[DD * 3];
    int tid = threadIdx.x;
    for (int i = tid; i < DD * 3; i += blockDim.x) sw[i] = head_w[i];
    __syncthreads();

    int row = (int)((blockIdx.x * (size_t)blockDim.x + tid) >> 5);
    int lane = tid & 31;
    if (row >= BB * NN) return;

    const float4* hrow =
        reinterpret_cast<const float4*>(hand_tokens + (size_t)row * DD);
    float4 a = hrow[lane];
    float4 c = hrow[lane + 32];

    float acc0 = 0.f, acc1 = 0.f, acc2 = 0.f;
    int d0 = lane * 4;
    {
        const float* w = &sw[d0 * 3];
        acc0 += a.x * w[0] + a.y * w[3] + a.z * w[6] + a.w * w[9];
        acc1 += a.x * w[1] + a.y * w[4] + a.z * w[7] + a.w * w[10];
        acc2 += a.x * w[2] + a.y * w[5] + a.z * w[8] + a.w * w[11];
    }
    {
        const float* w = &sw[(d0 + 128) * 3];
        acc0 += c.x * w[0] + c.y * w[3] + c.z * w[6] + c.w * w[9];
        acc1 += c.x * w[1] + c.y * w[4] + c.z * w[7] + c.w * w[10];
        acc2 += c.x * w[2] + c.y * w[5] + c.z * w[8] + c.w * w[11];
    }

#pragma unroll
    for (int off = 16; off > 0; off >>= 1) {
        acc0 += __shfl_xor_sync(0xFFFFFFFFu, acc0, off);
        acc1 += __shfl_xor_sync(0xFFFFFFFFu, acc1, off);
        acc2 += __shfl_xor_sync(0xFFFFFFFFu, acc2, off);
    }

    if (lane == 0) {
        int b = row / NN;
        int node = row - b * NN;
        float tau = fmaxf(1.0f - timesteps[b], TAU_MIN_F);
        size_t o = 3 * (size_t)row;
        float px = keypoints[o + 0] + tau * (acc0 + head_b[0]);
        float py = keypoints[o + 1] + tau * (acc1 + head_b[1]);
        float pz = keypoints[o + 2] + tau * (acc2 + head_b[2]);
        int base = node * 12 + b * 3;
        g_x[0][base + 0] = px;
        g_x[0][base + 1] = py;
        g_x[0][base + 2] = pz;
        g_x[1][base + 0] = px;  // pre-copy for iteration 0's scatter target
        g_x[1][base + 1] = py;
        g_x[1][base + 2] = pz;
    }
}

// ---------------------------------------------------------------------------
// Kernel 2: one XPBD Jacobi iteration, 2 edges per thread.
// All 12 position LDG.128 batched up front (MLP), corrections computed
// in-place over the load registers, then 12 v4 REDs issued back-to-back.
// ---------------------------------------------------------------------------
__device__ __forceinline__ void red_add_v4(const float* ptr, float a, float b,
                                           float c, float d) {
    asm volatile("red.global.add.v4.f32 [%0], {%1, %2, %3, %4};"
                 :: "l"(ptr), "f"(a), "f"(b), "f"(c), "f"(d)
                 : "memory");
}

__device__ __forceinline__ void corr_inplace(float* S, const float* D,
                                             float L0) {
#pragma unroll
    for (int b = 0; b < BB; b++) {
        float dx = S[b * 3 + 0] - D[b * 3 + 0];
        float dy = S[b * 3 + 1] - D[b * 3 + 1];
        float dz = S[b * 3 + 2] - D[b * 3 + 2];
        float d2 = fmaf(dx, dx, fmaf(dy, dy, dz * dz)) + 1e-24f;
        float rinv = rsqrtf(d2);
        float dist = d2 * rinv;
        float f = (L0 - dist) * 0.5f * rinv;
        S[b * 3 + 0] = fminf(fmaxf(f * dx, -MAX_CORR_F), MAX_CORR_F);
        S[b * 3 + 1] = fminf(fmaxf(f * dy, -MAX_CORR_F), MAX_CORR_F);
        S[b * 3 + 2] = fminf(fmaxf(f * dz, -MAX_CORR_F), MAX_CORR_F);
    }
}

__global__ void __launch_bounds__(256) edge_kernel(
    const int* __restrict__ edge_index, const float* __restrict__ rest,
    int cur, int nxt) {
    int t = blockIdx.x * blockDim.x + threadIdx.x;
    int e0 = t * 2;
    if (e0 >= EE) return;  // EE even: e0+1 always valid when e0 < EE

    int2 ss = *reinterpret_cast<const int2*>(&edge_index[e0]);
    int2 dd = *reinterpret_cast<const int2*>(&edge_index[EE + e0]);
    float2 LL = *reinterpret_cast<const float2*>(&rest[e0]);

    const float4* S0p = reinterpret_cast<const float4*>(&g_x[cur][ss.x * 12]);
    const float4* D0p = reinterpret_cast<const float4*>(&g_x[cur][dd.x * 12]);
    const float4* S1p = reinterpret_cast<const float4*>(&g_x[cur][ss.y * 12]);
    const float4* D1p = reinterpret_cast<const float4*>(&g_x[cur][dd.y * 12]);

    float S0[12], D0[12], S1[12], D1[12];
#pragma unroll
    for (int k = 0; k < 3; k++) {
        reinterpret_cast<float4*>(S0)[k] = S0p[k];
        reinterpret_cast<float4*>(D0)[k] = D0p[k];
        reinterpret_cast<float4*>(S1)[k] = S1p[k];
        reinterpret_cast<float4*>(D1)[k] = D1p[k];
    }

    corr_inplace(S0, D0, LL.x);   // S0 now holds C0
    corr_inplace(S1, D1, LL.y);   // S1 now holds C1

    const float* oS0 = &g_x[nxt][ss.x * 12];
    const float* oD0 = &g_x[nxt][dd.x * 12];
    const float* oS1 = &g_x[nxt][ss.y * 12];
    const float* oD1 = &g_x[nxt][dd.y * 12];

    red_add_v4(oS0 + 0, S0[0], S0[1], S0[2], S0[3]);
    red_add_v4(oS0 + 4, S0[4], S0[5], S0[6], S0[7]);
    red_add_v4(oS0 + 8, S0[8], S0[9], S0[10], S0[11]);
    red_add_v4(oD0 + 0, -S0[0], -S0[1], -S0[2], -S0[3]);
    red_add_v4(oD0 + 4, -S0[4], -S0[5], -S0[6], -S0[7]);
    red_add_v4(oD0 + 8, -S0[8], -S0[9], -S0[10], -S0[11]);
    red_add_v4(oS1 + 0, S1[0], S1[1], S1[2], S1[3]);
    red_add_v4(oS1 + 4, S1[4], S1[5], S1[6], S1[7]);
    red_add_v4(oS1 + 8, S1[8], S1[9], S1[10], S1[11]);
    red_add_v4(oD1 + 0, -S1[0], -S1[1], -S1[2], -S1[3]);
    red_add_v4(oD1 + 4, -S1[4], -S1[5], -S1[6], -S1[7]);
    red_add_v4(oD1 + 8, -S1[8], -S1[9], -S1[10], -S1[11]);
}

// ---------------------------------------------------------------------------
// Kernel 3: v_eff = (x_corrected - keypoints) / tau
// ---------------------------------------------------------------------------
__global__ void final_kernel(const float* __restrict__ keypoints,
                             const float* __restrict__ timesteps,
                             float* __restrict__ out, int cur) {
    int i = blockIdx.x * blockDim.x + threadIdx.x;
    if (i >= BB * NN) return;
    int b = i / NN;
    int node = i - b * NN;
    float tau = fmaxf(1.0f - timesteps[b], TAU_MIN_F);
    int base = node * 12 + b * 3;
    size_t o = 3 * (size_t)i;
    out[o + 0] = (g_x[cur][base + 0] - keypoints[o + 0]) / tau;
    out[o + 1] = (g_x[cur][base + 1] - keypoints[o + 1]) / tau;
    out[o + 2] = (g_x[cur][base + 2] - keypoints[o + 2]) / tau;
}

extern "C" void kernel_launch(void* const* d_in, const int* in_sizes, int n_in,
                              void* d_out, int out_size) {
    const float* keypoints = (const float*)d_in[0];
    const float* timesteps = (const float*)d_in[1];
    const float* hand_tokens = (const float*)d_in[2];
    const float* head_w = (const float*)d_in[3];
    const float* head_b = (const float*)d_in[4];
    const int* edge_index = (const int*)d_in[5];
    const float* rest = (const float*)d_in[6];
    float* out = (float*)d_out;

    const int rows = BB * NN;  // 200000

    float* x_base = nullptr;
    cudaGetSymbolAddress((void**)&x_base, g_x);

    // Phase 1: prediction head (writes both ping-pong buffers)
    {
        long long threads = (long long)rows * 32;
        pred_kernel<<<(int)((threads + 255) / 256), 256>>>(
            keypoints, timesteps, hand_tokens, head_w, head_b);
    }

    // Phase 2: XPBD Jacobi iterations (scatter with packed v4 REDs)
    int cur = 0;
    const int pairs = EE / 2;
    for (int it = 0; it < XPBD_ITERS_I; it++) {
        int nxt = cur ^ 1;
        if (it > 0) {
            cudaMemcpyAsync(x_base + (size_t)nxt * XN,
                            x_base + (size_t)cur * XN, XN * sizeof(float),
                            cudaMemcpyDeviceToDevice);
        }
        edge_kernel<<<(pairs + 255) / 256, 256>>>(edge_index, rest, cur, nxt);
        cur = nxt;
    }

    // Phase 3: effective velocity
    final_kernel<<<(rows + 255) / 256, 256>>>(keypoints, timesteps, out, cur);
}